// round 13
// baseline (speedup 1.0000x reference)
#include <cuda_runtime.h>
#include <cuda_bf16.h>
#include <cstring>

#define BB 128
#define TT 512
#define II 128
#define HH 256

__device__ float g_xp[(size_t)BB * TT * HH];   // [B][T][H] fp32 scratch (fits L2)

// Packed fp32x2 FMA (sm_103a).
__device__ __forceinline__ float2 ffma2(float2 a, float2 b, float2 c) {
    unsigned long long ua, ub, uc, ud;
    memcpy(&ua, &a, 8); memcpy(&ub, &b, 8); memcpy(&uc, &c, 8);
    asm("fma.rn.f32x2 %0, %1, %2, %3;" : "=l"(ud) : "l"(ua), "l"(ub), "l"(uc));
    float2 d; memcpy(&d, &ud, 8); return d;
}

// Safe fast tanh: e = exp(-2|x|) in (0,1] -> no overflow; validated rel_err 6e-8.
__device__ __forceinline__ float fast_tanh(float x) {
    float e = __expf(-2.0f * fabsf(x));
    float r = __fdividef(1.0f - e, 1.0f + e);
    return copysignf(r, x);
}

// Pack two fp32 -> one u32 of bf16 (round-to-nearest), lo in low half.
__device__ __forceinline__ unsigned f2_to_bf2(float a, float b) {
    unsigned short ua = __bfloat16_as_ushort(__float2bfloat16_rn(a));
    unsigned short ub = __bfloat16_as_ushort(__float2bfloat16_rn(b));
    return (unsigned)ua | ((unsigned)ub << 16);
}

// Decompress pair: lo needs one shift; hi uses the u32 reinterpreted DIRECTLY
// (low 16 garbage bits perturb by <=2^-9 relative — same scale as the bf16
// rounding already accepted). 1 ALU op per u32.
__device__ __forceinline__ float2 bf2_lo_higarbage(unsigned u) {
    float2 r;
    r.x = __uint_as_float(u << 16);
    r.y = __uint_as_float(u);
    return r;
}

// ---------------------------------------------------------------------------
// Phase 1: xp[r,h] = x[r,:] . W_ih[h,:] + (b_ih[h] + b_hh[h])
// PARITY-PAIR LAYOUT: 128 CTAs x 512 threads (16 warps, 4/SMSP). Unchanged
// (fp32 exact — xp error feeds every step, keep it clean).
// ---------------------------------------------------------------------------
__global__ void __launch_bounds__(512, 1)
rnn_xproj(const float* __restrict__ x,
          const float* __restrict__ W_ih,
          const float* __restrict__ b_ih,
          const float* __restrict__ b_hh) {
    __shared__ float xs[2][8 * II];               // 2 x 4 KB (8 rows/tile)

    const int tid  = threadIdx.x;
    const int lane = tid & 31;
    const int w    = tid >> 5;
    const int j    = (w << 4) | (lane >> 1);      // feature 0..255
    const int p    = lane & 1;

    const float4* Wi4 = (const float4*)W_ih;      // row j = Wi4[j*32 .. +31]
    float4 wreg[16];
#pragma unroll
    for (int qq = 0; qq < 16; qq++) wreg[qq] = Wi4[j * 32 + 2 * qq + p];

    const float bias = b_ih[j] + b_hh[j];
    const size_t base_row = (size_t)blockIdx.x * 512;

    if (tid < 256)
        ((float4*)xs[0])[tid] = ((const float4*)(x + base_row * II))[tid];
    __syncthreads();

    for (int tile = 0; tile < 64; tile++) {
        const int cur = tile & 1;
        if (tile < 63 && tid < 256) {
            ((float4*)xs[cur ^ 1])[tid] =
                ((const float4*)(x + (base_row + (size_t)(tile + 1) * 8) * II))[tid];
        }

        const size_t r0 = base_row + (size_t)tile * 8;
#pragma unroll
        for (int r = 0; r < 8; r++) {
            const float4* xr = (const float4*)(xs[cur] + r * II);
            float2 a0 = make_float2(0.0f, 0.0f), a1 = a0, a2 = a0, a3 = a0;
#pragma unroll
            for (int qq = 0; qq < 16; qq++) {
                float4 xv = xr[2 * qq + p];
                if (qq & 1) {
                    a2 = ffma2(make_float2(xv.x, xv.y), make_float2(wreg[qq].x, wreg[qq].y), a2);
                    a3 = ffma2(make_float2(xv.z, xv.w), make_float2(wreg[qq].z, wreg[qq].w), a3);
                } else {
                    a0 = ffma2(make_float2(xv.x, xv.y), make_float2(wreg[qq].x, wreg[qq].y), a0);
                    a1 = ffma2(make_float2(xv.z, xv.w), make_float2(wreg[qq].z, wreg[qq].w), a1);
                }
            }
            float dot = ((a0.x + a0.y) + (a1.x + a1.y)) +
                        ((a2.x + a2.y) + (a3.x + a3.y));
            dot += __shfl_xor_sync(0xffffffffu, dot, 1);   // combine parities
            if (p == 0)
                g_xp[(r0 + r) * HH + j] = dot + bias;      // 16 consec floats/warp
        }
        __syncthreads();
    }
}

// ---------------------------------------------------------------------------
// Phase 2 + 3: recurrent scan — ALL-REGISTER BF16 W (no SMEM weight tail).
// PARITY-PAIR LAYOUT: warp w, lane l -> feature j = w*16 + (l>>1), p = l&1.
// Thread (j,p) holds its 128 W_hh values as 64 bf16-pair u32 REGISTERS.
// Per step: 32 broadcast h LDS.128 (1 wf each) + 64 shifts (ALU pipe) +
// 64 FFMA2 (FMA pipe) + shfl.xor(1) + publish + ONE __syncthreads.
// Crossbar/step drops from ~1230 wf (R12) to ~530 wf.
// ---------------------------------------------------------------------------
__global__ void __launch_bounds__(512, 1)
rnn_scan(const float* __restrict__ W_hh,
         const float* __restrict__ W_fc,
         const float* __restrict__ b_fc,
         float* __restrict__ out) {
    __shared__ float hA[HH];
    __shared__ float hB[HH];
    __shared__ float red[8];

    const int tid  = threadIdx.x;
    const int lane = tid & 31;
    const int w    = tid >> 5;
    const int j    = (w << 4) | (lane >> 1);    // 0..255
    const int p    = lane & 1;
    const int b    = blockIdx.x;

    const float4* W4 = (const float4*)W_hh;     // row j = W4[j*64 .. +63]

    // Pack the whole parity slice into 64 u32 registers.
    unsigned wbf[64];
#pragma unroll
    for (int qq = 0; qq < 32; qq++) {
        float4 f = W4[j * 64 + 2 * qq + p];
        wbf[2 * qq]     = f2_to_bf2(f.x, f.y);
        wbf[2 * qq + 1] = f2_to_bf2(f.z, f.w);
    }

    if (tid < HH) { hA[tid] = 0.0f; hB[tid] = 0.0f; }
    __syncthreads();

    const float* xp = g_xp + (size_t)b * TT * HH + j;

    float* hcur = hA;
    float* hnxt = hB;

    float xpv = xp[0];                          // pipeline head

    for (int t = 0; t < TT; t++) {
        const float4* hs4 = (const float4*)hcur;
        float2 a0 = make_float2(0.0f, 0.0f), a1 = a0, a2 = a0, a3 = a0;

#pragma unroll
        for (int qq = 0; qq < 32; qq++) {
            float4 h4 = hs4[2 * qq + p];        // broadcast pair: 1 wavefront
            float2 w0 = bf2_lo_higarbage(wbf[2 * qq]);
            float2 w1 = bf2_lo_higarbage(wbf[2 * qq + 1]);
            if (qq & 1) {
                a2 = ffma2(make_float2(h4.x, h4.y), w0, a2);
                a3 = ffma2(make_float2(h4.z, h4.w), w1, a3);
            } else {
                a0 = ffma2(make_float2(h4.x, h4.y), w0, a0);
                a1 = ffma2(make_float2(h4.z, h4.w), w1, a1);
            }
        }

        // prefetch next step's xp while the exchange/tanh drains
        float xpn = 0.0f;
        if (t + 1 < TT) xpn = xp[(size_t)(t + 1) * HH];

        const float mydot = ((a0.x + a0.y) + (a1.x + a1.y)) +
                            ((a2.x + a2.y) + (a3.x + a3.y));

        const float other = __shfl_xor_sync(0xffffffffu, mydot, 1);
        const float hn = fast_tanh(xpv + mydot + other);  // identical in pair

        if (p == 0) hnxt[j] = hn;               // even lanes publish
        __syncthreads();                        // single barrier per step

        xpv = xpn;
        float* tmp = hcur; hcur = hnxt; hnxt = tmp;
    }

    // Phase 3: out[b] = sigmoid(h . W_fc + b_fc)
    if (tid < HH) {
        float v = hcur[tid] * W_fc[tid];
#pragma unroll
        for (int o = 16; o > 0; o >>= 1) v += __shfl_down_sync(0xffffffffu, v, o);
        if ((tid & 31) == 0) red[tid >> 5] = v;
    }
    __syncthreads();
    if (tid == 0) {
        float s = b_fc[0];
#pragma unroll
        for (int w2 = 0; w2 < 8; w2++) s += red[w2];
        out[b] = 1.0f / (1.0f + expf(-s));
    }
}

// ---------------------------------------------------------------------------

extern "C" void kernel_launch(void* const* d_in, const int* in_sizes, int n_in,
                              void* d_out, int out_size) {
    const float* x    = (const float*)d_in[0];
    const float* W_ih = (const float*)d_in[1];
    const float* W_hh = (const float*)d_in[2];
    const float* b_ih = (const float*)d_in[3];
    const float* b_hh = (const float*)d_in[4];
    const float* W_fc = (const float*)d_in[5];
    const float* b_fc = (const float*)d_in[6];
    float* out = (float*)d_out;

    rnn_xproj<<<128, 512>>>(x, W_ih, b_ih, b_hh);
    rnn_scan<<<BB, 512>>>(W_hh, W_fc, b_fc, out);
}

// round 14
// speedup vs baseline: 1.4376x; 1.4376x over previous
#include <cuda_runtime.h>
#include <cuda_bf16.h>
#include <cstring>

#define BB 128
#define TT 512
#define II 128
#define HH 256

__device__ float g_xp[(size_t)BB * TT * HH];   // [B][T][H] fp32 scratch (fits L2)

// Packed fp32x2 FMA (sm_103a).
__device__ __forceinline__ float2 ffma2(float2 a, float2 b, float2 c) {
    unsigned long long ua, ub, uc, ud;
    memcpy(&ua, &a, 8); memcpy(&ub, &b, 8); memcpy(&uc, &c, 8);
    asm("fma.rn.f32x2 %0, %1, %2, %3;" : "=l"(ud) : "l"(ua), "l"(ub), "l"(uc));
    float2 d; memcpy(&d, &ud, 8); return d;
}

// Safe fast tanh: e = exp(-2|x|) in (0,1] -> no overflow; validated rel_err 6e-8.
__device__ __forceinline__ float fast_tanh(float x) {
    float e = __expf(-2.0f * fabsf(x));
    float r = __fdividef(1.0f - e, 1.0f + e);
    return copysignf(r, x);
}

// Pack two fp32 -> one u32 of bf16 (round-to-nearest), lo in low half.
__device__ __forceinline__ unsigned f2_to_bf2(float a, float b) {
    unsigned short ua = __bfloat16_as_ushort(__float2bfloat16_rn(a));
    unsigned short ub = __bfloat16_as_ushort(__float2bfloat16_rn(b));
    return (unsigned)ua | ((unsigned)ub << 16);
}

// Decompress pair: lo = one shift; hi = u32 reinterpreted directly (low 16
// garbage bits perturb <=2^-9 relative — same scale as bf16 rounding;
// VALIDATED R13: full-bf16 W with this trick -> rel_err 1.78e-4).
__device__ __forceinline__ float2 bf2_lo_higarbage(unsigned u) {
    float2 r;
    r.x = __uint_as_float(u << 16);
    r.y = __uint_as_float(u);
    return r;
}

// ---------------------------------------------------------------------------
// Phase 1: xp[r,h] = x[r,:] . W_ih[h,:] + (b_ih[h] + b_hh[h])
// PARITY-PAIR LAYOUT: 128 CTAs x 512 threads (16 warps, 4/SMSP). Unchanged
// (fp32 exact — xp error feeds every step, keep it clean).
// ---------------------------------------------------------------------------
__global__ void __launch_bounds__(512, 1)
rnn_xproj(const float* __restrict__ x,
          const float* __restrict__ W_ih,
          const float* __restrict__ b_ih,
          const float* __restrict__ b_hh) {
    __shared__ float xs[2][8 * II];               // 2 x 4 KB (8 rows/tile)

    const int tid  = threadIdx.x;
    const int lane = tid & 31;
    const int w    = tid >> 5;
    const int j    = (w << 4) | (lane >> 1);      // feature 0..255
    const int p    = lane & 1;

    const float4* Wi4 = (const float4*)W_ih;      // row j = Wi4[j*32 .. +31]
    float4 wreg[16];
#pragma unroll
    for (int qq = 0; qq < 16; qq++) wreg[qq] = Wi4[j * 32 + 2 * qq + p];

    const float bias = b_ih[j] + b_hh[j];
    const size_t base_row = (size_t)blockIdx.x * 512;

    if (tid < 256)
        ((float4*)xs[0])[tid] = ((const float4*)(x + base_row * II))[tid];
    __syncthreads();

    for (int tile = 0; tile < 64; tile++) {
        const int cur = tile & 1;
        if (tile < 63 && tid < 256) {
            ((float4*)xs[cur ^ 1])[tid] =
                ((const float4*)(x + (base_row + (size_t)(tile + 1) * 8) * II))[tid];
        }

        const size_t r0 = base_row + (size_t)tile * 8;
#pragma unroll
        for (int r = 0; r < 8; r++) {
            const float4* xr = (const float4*)(xs[cur] + r * II);
            float2 a0 = make_float2(0.0f, 0.0f), a1 = a0, a2 = a0, a3 = a0;
#pragma unroll
            for (int qq = 0; qq < 16; qq++) {
                float4 xv = xr[2 * qq + p];
                if (qq & 1) {
                    a2 = ffma2(make_float2(xv.x, xv.y), make_float2(wreg[qq].x, wreg[qq].y), a2);
                    a3 = ffma2(make_float2(xv.z, xv.w), make_float2(wreg[qq].z, wreg[qq].w), a3);
                } else {
                    a0 = ffma2(make_float2(xv.x, xv.y), make_float2(wreg[qq].x, wreg[qq].y), a0);
                    a1 = ffma2(make_float2(xv.z, xv.w), make_float2(wreg[qq].z, wreg[qq].w), a1);
                }
            }
            float dot = ((a0.x + a0.y) + (a1.x + a1.y)) +
                        ((a2.x + a2.y) + (a3.x + a3.y));
            dot += __shfl_xor_sync(0xffffffffu, dot, 1);   // combine parities
            if (p == 0)
                g_xp[(r0 + r) * HH + j] = dot + bias;      // 16 consec floats/warp
        }
        __syncthreads();
    }
}

// ---------------------------------------------------------------------------
// Phase 2 + 3: recurrent scan — ALL-BF16 W, split 96-in-regs / 32-in-SMEM.
// PARITY-PAIR LAYOUT: warp w, lane l -> feature j = w*16 + (l>>1), p = l&1.
// Thread (j,p) covers h/W float4 indices {2*qq + p}, qq = 0..31:
//   qq <  24: W as 48 bf16-pair u32 REGISTERS (96 weights, 48 regs —
//             R13's 64-reg version spilled; this leaves ~40 regs headroom).
//   qq >= 24: W as 4 uint4 bf16 loads from SMEM (32 weights, 256 wf/step).
// Per step: 32 broadcast h LDS.128 (1 wf each) + 4 tail uint4 + decompress
// on ALU pipe + 64 FFMA2 + shfl.xor(1) + publish + ONE __syncthreads.
// ---------------------------------------------------------------------------
#define NRQ 24            // qq covered by registers
#define NTS 4             // SMEM tail uint4 per thread (covers qq 24..31)

__global__ void __launch_bounds__(512, 1)
rnn_scan(const float* __restrict__ W_hh,
         const float* __restrict__ W_fc,
         const float* __restrict__ b_fc,
         float* __restrict__ out) {
    extern __shared__ float sm[];
    uint4* wtU = (uint4*)sm;                    // [NTS][512] uint4 = 32 KB
    float* hA  = sm + NTS * 512 * 4;            // 256 floats
    float* hB  = hA + HH;                       // 256 floats
    float* red = hB + HH;                       // 8 floats

    const int tid  = threadIdx.x;
    const int lane = tid & 31;
    const int w    = tid >> 5;
    const int j    = (w << 4) | (lane >> 1);    // 0..255
    const int p    = lane & 1;
    const int b    = blockIdx.x;

    const float4* W4 = (const float4*)W_hh;     // row j = W4[j*64 .. +63]

    // 96 weights -> 48 bf16-pair registers (qq = 0..23)
    unsigned wbf[48];
#pragma unroll
    for (int qq = 0; qq < NRQ; qq++) {
        float4 f = W4[j * 64 + 2 * qq + p];
        wbf[2 * qq]     = f2_to_bf2(f.x, f.y);
        wbf[2 * qq + 1] = f2_to_bf2(f.z, f.w);
    }

    // 32 weights -> 4 uint4 in SMEM (slot s covers qq = NRQ+2s, NRQ+2s+1)
#pragma unroll
    for (int s = 0; s < NTS; s++) {
        float4 fa = W4[j * 64 + 2 * (NRQ + 2 * s) + p];
        float4 fb = W4[j * 64 + 2 * (NRQ + 2 * s + 1) + p];
        uint4 u;
        u.x = f2_to_bf2(fa.x, fa.y);
        u.y = f2_to_bf2(fa.z, fa.w);
        u.z = f2_to_bf2(fb.x, fb.y);
        u.w = f2_to_bf2(fb.z, fb.w);
        wtU[s * 512 + j * 2 + p] = u;
    }

    if (tid < HH) { hA[tid] = 0.0f; hB[tid] = 0.0f; }
    __syncthreads();

    const float* xp  = g_xp + (size_t)b * TT * HH + j;
    const uint4* wtp = wtU + j * 2 + p;         // wtp[s*512]

    float* hcur = hA;
    float* hnxt = hB;

    float xpv = xp[0];                          // pipeline head

    for (int t = 0; t < TT; t++) {
        const float4* hs4 = (const float4*)hcur;
        float2 a0 = make_float2(0.0f, 0.0f), a1 = a0, a2 = a0, a3 = a0;

        // SMEM bf16 tail first: LDS latency overlaps the register-W stream
#pragma unroll
        for (int s = 0; s < NTS; s++) {
            uint4 wv = wtp[s * 512];
            float4 ha = hs4[2 * (NRQ + 2 * s) + p];
            float4 hb = hs4[2 * (NRQ + 2 * s + 1) + p];
            a0 = ffma2(make_float2(ha.x, ha.y), bf2_lo_higarbage(wv.x), a0);
            a1 = ffma2(make_float2(ha.z, ha.w), bf2_lo_higarbage(wv.y), a1);
            a2 = ffma2(make_float2(hb.x, hb.y), bf2_lo_higarbage(wv.z), a2);
            a3 = ffma2(make_float2(hb.z, hb.w), bf2_lo_higarbage(wv.w), a3);
        }
        // Register-resident bf16 W (qq = 0..23)
#pragma unroll
        for (int qq = 0; qq < NRQ; qq++) {
            float4 h4 = hs4[2 * qq + p];        // broadcast pair: 1 wavefront
            float2 w0 = bf2_lo_higarbage(wbf[2 * qq]);
            float2 w1 = bf2_lo_higarbage(wbf[2 * qq + 1]);
            if (qq & 1) {
                a2 = ffma2(make_float2(h4.x, h4.y), w0, a2);
                a3 = ffma2(make_float2(h4.z, h4.w), w1, a3);
            } else {
                a0 = ffma2(make_float2(h4.x, h4.y), w0, a0);
                a1 = ffma2(make_float2(h4.z, h4.w), w1, a1);
            }
        }

        // prefetch next step's xp while the exchange/tanh drains
        float xpn = 0.0f;
        if (t + 1 < TT) xpn = xp[(size_t)(t + 1) * HH];

        const float mydot = ((a0.x + a0.y) + (a1.x + a1.y)) +
                            ((a2.x + a2.y) + (a3.x + a3.y));

        const float other = __shfl_xor_sync(0xffffffffu, mydot, 1);
        const float hn = fast_tanh(xpv + mydot + other);  // identical in pair

        if (p == 0) hnxt[j] = hn;               // even lanes publish
        __syncthreads();                        // single barrier per step

        xpv = xpn;
        float* tmp = hcur; hcur = hnxt; hnxt = tmp;
    }

    // Phase 3: out[b] = sigmoid(h . W_fc + b_fc)
    if (tid < HH) {
        float v = hcur[tid] * W_fc[tid];
#pragma unroll
        for (int o = 16; o > 0; o >>= 1) v += __shfl_down_sync(0xffffffffu, v, o);
        if ((tid & 31) == 0) red[tid >> 5] = v;
    }
    __syncthreads();
    if (tid == 0) {
        float s = b_fc[0];
#pragma unroll
        for (int w2 = 0; w2 < 8; w2++) s += red[w2];
        out[b] = 1.0f / (1.0f + expf(-s));
    }
}

// ---------------------------------------------------------------------------

extern "C" void kernel_launch(void* const* d_in, const int* in_sizes, int n_in,
                              void* d_out, int out_size) {
    const float* x    = (const float*)d_in[0];
    const float* W_ih = (const float*)d_in[1];
    const float* W_hh = (const float*)d_in[2];
    const float* b_ih = (const float*)d_in[3];
    const float* b_hh = (const float*)d_in[4];
    const float* W_fc = (const float*)d_in[5];
    const float* b_fc = (const float*)d_in[6];
    float* out = (float*)d_out;

    const int smem_b = (NTS * 512 * 4 + 2 * HH + 8) * (int)sizeof(float);  // ~34 KB
    cudaFuncSetAttribute(rnn_scan, cudaFuncAttributeMaxDynamicSharedMemorySize, smem_b);

    rnn_xproj<<<128, 512>>>(x, W_ih, b_ih, b_hh);
    rnn_scan<<<BB, 512, smem_b>>>(W_hh, W_fc, b_fc, out);
}